// round 9
// baseline (speedup 1.0000x reference)
#include <cuda_runtime.h>
#include <cuda_fp16.h>

#define N_TASK 50000
#define N_RET  20000
#define N_DRAM 5000
#define N_LINKN 100000
#define E_RET  1000000
#define E_DRAM 250000
#define E_LINK 2000000
#define HD 64
#define SCAN_NBLK 98   /* ceil(100000/1024) */

// ---------------- device scratch ----------------
__device__ float    g_s_ret[N_RET];
__device__ float    g_s_dram[N_DRAM];
__device__ float2   g_sc_link[N_LINKN];   // (sum, count) -> after scan: (sum, offs-bits)
__device__ uint2    g_mm[3 * N_TASK];     // (max_enc, min_enc) per (etype, task)
__device__ __half   g_h_task[N_TASK * HD];
__device__ int      g_cnt[N_LINKN];
__device__ int      g_offs[N_LINKN];
__device__ int      g_rank[E_LINK];       // edge's rank within its module
__device__ int      g_csr[E_LINK];
__device__ int      g_part[128];
__device__ int      g_done;

// order-preserving float<->uint encoding (all real floats encode > 0)
__device__ __forceinline__ unsigned encf(float f) {
    unsigned u = __float_as_uint(f);
    return (u & 0x80000000u) ? ~u : (u | 0x80000000u);
}
__device__ __forceinline__ float decf(unsigned u) {
    return __uint_as_float((u & 0x80000000u) ? (u & 0x7FFFFFFFu) : ~u);
}

__device__ __forceinline__ float tanh_fast(float x) {
    float y;
    asm("tanh.approx.f32 %0, %1;" : "=f"(y) : "f"(x));
    return y;
}

// ---------------- init (g_mm init moved into k_sum tail) ----------------
__global__ void k_init() {
    int i = blockIdx.x * blockDim.x + threadIdx.x;
    if (i == 0) g_done = 0;
    if (i < N_RET)  g_s_ret[i]  = 0.f;
    if (i < N_DRAM) g_s_dram[i] = 0.f;
    if (i < N_LINKN) g_sc_link[i] = make_float2(0.f, 0.f);
}

// ---------------- fused segment sums + g_mm init: 1 edge / thread ---------
#define NE_ALL (E_LINK + E_RET + E_DRAM)
__global__ void k_sum(const float* __restrict__ fl, const int* __restrict__ ml,
                      const float* __restrict__ fr, const int* __restrict__ mr,
                      const float* __restrict__ fd, const int* __restrict__ md) {
    int i = blockIdx.x * blockDim.x + threadIdx.x;
    if (i < E_LINK) {
        int m = __ldg(&ml[i]);
        float2 old = atomicAdd(&g_sc_link[m], make_float2(__ldg(&fl[i]), 1.0f));
        g_rank[i] = (int)old.y;           // this edge's rank within module m
    } else if (i < E_LINK + E_RET) {
        int j = i - E_LINK;
        atomicAdd(&g_s_ret[__ldg(&mr[j])], __ldg(&fr[j]));
    } else if (i < NE_ALL) {
        int j = i - E_LINK - E_RET;
        atomicAdd(&g_s_dram[__ldg(&md[j])], __ldg(&fd[j]));
    } else if (i < NE_ALL + 3 * N_TASK) {
        g_mm[i - NE_ALL] = make_uint2(0u, 0xFFFFFFFFu);   // init for minmax
    }
}

// ---------------- fused: scan (bids 0..97, spin-join) + ret/dram minmax ---
// scan blocks are in wave 1 (98 << 148*8 resident blocks) -> spin is safe.
__global__ void k_fuse(const int* __restrict__ mr, const int* __restrict__ tr,
                       const int* __restrict__ md, const int* __restrict__ td) {
    if (blockIdx.x < SCAN_NBLK) {
        __shared__ int sh[256];
        int b = blockIdx.x, tid = threadIdx.x;
        int i = b * 1024 + tid * 4;

        int c0 = 0, c1 = 0, c2 = 0, c3 = 0, s = 0;
        if (i < N_LINKN) {
            float4 a = *(const float4*)&g_sc_link[i];
            float4 d = *(const float4*)&g_sc_link[i + 2];
            c0 = (int)a.y; c1 = (int)a.w; c2 = (int)d.y; c3 = (int)d.w;
            s = c0 + c1 + c2 + c3;
        }

        sh[tid] = s;
        __syncthreads();
        for (int off = 1; off < 256; off <<= 1) {
            int u = (tid >= off) ? sh[tid - off] : 0;
            __syncthreads();
            sh[tid] += u;
            __syncthreads();
        }
        int incl = sh[tid];
        int blk_total = sh[255];

        if (tid == 0) {
            g_part[b] = blk_total;
            __threadfence();
            atomicAdd(&g_done, 1);
            while (*(volatile int*)&g_done < SCAN_NBLK) { }
        }
        __syncthreads();

        sh[tid] = (tid < b) ? ((volatile int*)g_part)[tid] : 0;
        __syncthreads();
        for (int off = 128; off > 0; off >>= 1) {
            if (tid < off) sh[tid] += sh[tid + off];
            __syncthreads();
        }
        int base = sh[0];

        int run = base + incl - s;
        if (i < N_LINKN) {
            int4 o;
            o.x = run;
            o.y = run + c0;
            o.z = o.y + c1;
            o.w = o.z + c2;
            *(int4*)&g_offs[i] = o;
            *(int4*)&g_cnt[i]  = make_int4(c0, c1, c2, c3);
            int2* scl = (int2*)g_sc_link;
            scl[i + 0].y = o.x;
            scl[i + 1].y = o.y;
            scl[i + 2].y = o.z;
            scl[i + 3].y = o.w;
        }
    } else {
        int i = (blockIdx.x - SCAN_NBLK) * blockDim.x + threadIdx.x;
        if (i < E_RET) {
            unsigned k = encf(g_s_ret[__ldg(&mr[i])]);
            int t = __ldg(&tr[i]);
            atomicMax(&g_mm[0 * N_TASK + t].x, k);
            atomicMin(&g_mm[0 * N_TASK + t].y, k);
        } else if (i < E_RET + E_DRAM) {
            int j = i - E_RET;
            unsigned k = encf(g_s_dram[__ldg(&md[j])]);
            int t = __ldg(&td[j]);
            atomicMax(&g_mm[1 * N_TASK + t].x, k);
            atomicMin(&g_mm[1 * N_TASK + t].y, k);
        }
    }
}

// ---------------- link min/max + CSR scatter (rank trick) -----------------
__global__ void k_mm_link(const int* __restrict__ ml, const int* __restrict__ tl) {
    int i = blockIdx.x * blockDim.x + threadIdx.x;
    if (i >= E_LINK) return;
    int m = __ldg(&ml[i]);
    int t = __ldg(&tl[i]);
    float2 sc = *(const float2*)&g_sc_link[m];   // one 8B scattered load
    unsigned k = encf(sc.x);
    atomicMax(&g_mm[2 * N_TASK + t].x, k);
    atomicMin(&g_mm[2 * N_TASK + t].y, k);
    int p = __float_as_int(sc.y) + __ldg(&g_rank[i]);
    g_csr[p] = t;
}

// ---------------- task update: tanh(v @ Wtask^T + b), f32x2 FFMA ----------
__global__ void k_task(const float* __restrict__ Wret,  const float* __restrict__ bret,
                       const float* __restrict__ Wdram, const float* __restrict__ bdram,
                       const float* __restrict__ Wlink, const float* __restrict__ blink,
                       const float* __restrict__ Wtask, const float* __restrict__ btask) {
    extern __shared__ float sh[];
    float*  sV  = sh;                                   // 12288 floats
    float2* sW2 = (float2*)(sh + 64 * 192);             // 64*97 float2
    uint2*  sMM = (uint2*)(sh + 64 * 192 + 64 * 97 * 2);// 192 uint2
    float*  sWe = (float*)(sMM + 192);                  // 192 floats
    float*  sBe = sWe + 192;                            // 192 floats

    int tb = blockIdx.x * 64;
    int tid = threadIdx.x;

    if (tid < 192) {
        int et = tid >> 6, hh = tid & 63;
        const float* We = (et == 0) ? Wret : (et == 1) ? Wdram : Wlink;
        const float* be = (et == 0) ? bret : (et == 1) ? bdram : blink;
        sWe[tid] = We[hh];
        sBe[tid] = be[hh];
    }
    for (int idx = tid; idx < 64 * 3; idx += 256) {
        int tl = idx / 3, et = idx - tl * 3;
        int t = tb + tl;
        sMM[tl * 3 + et] = (t < N_TASK) ? g_mm[et * N_TASK + t]
                                        : make_uint2(0u, 0xFFFFFFFFu);
    }
    for (int idx = tid; idx < 64 * 96; idx += 256) {
        int h = idx / 96, kp = idx - h * 96;
        sW2[h * 97 + kp] = *(const float2*)&Wtask[h * 192 + 2 * kp];
    }
    __syncthreads();

    for (int idx = tid; idx < 64 * 192; idx += 256) {
        int tl = idx / 192, k = idx - tl * 192;
        int et = k >> 6, h = k & 63;
        float v = 0.f;
        uint2 mm = sMM[tl * 3 + et];
        if (mm.x != 0u) {
            float w = sWe[et * 64 + h];
            float sv = (w >= 0.f) ? decf(mm.x) : decf(mm.y);
            v = tanh_fast(fmaf(w, sv, sBe[et * 64 + h]));
        }
        sV[idx] = v;
    }
    __syncthreads();

    int tx = tid & 31, ty = tid >> 5;
    int h  = tx + 32 * (ty & 1);
    int t0 = 16 * (ty >> 1);

    unsigned long long acc[16];
#pragma unroll
    for (int i = 0; i < 16; i++) acc[i] = 0ull;

    const float2* wrow = sW2 + h * 97;
    const float*  vb   = sV + t0 * 192;

#pragma unroll 4
    for (int kp = 0; kp < 96; kp += 2) {
        unsigned long long w0 = *(const unsigned long long*)&wrow[kp];
        unsigned long long w1 = *(const unsigned long long*)&wrow[kp + 1];
#pragma unroll
        for (int i = 0; i < 16; i++) {
            ulonglong2 v = *(const ulonglong2*)(vb + i * 192 + 2 * kp);
            asm("fma.rn.f32x2 %0, %1, %2, %0;" : "+l"(acc[i]) : "l"(v.x), "l"(w0));
            asm("fma.rn.f32x2 %0, %1, %2, %0;" : "+l"(acc[i]) : "l"(v.y), "l"(w1));
        }
    }

    float bh = btask[h];
#pragma unroll
    for (int i = 0; i < 16; i++) {
        int t = tb + t0 + i;
        if (t < N_TASK) {
            float lo, hi;
            asm("mov.b64 {%0, %1}, %2;" : "=f"(lo), "=f"(hi) : "l"(acc[i]));
            g_h_task[t * 64 + h] = __float2half(tanh_fast(lo + hi + bh));
        }
    }
}

// ---------------- link mean: warp per link node, CSR gather (fp16 h) ------
__global__ void k_linkmean(float* __restrict__ out) {
    int gw = (blockIdx.x * blockDim.x + threadIdx.x) >> 5;
    if (gw >= N_LINKN) return;
    int lane = threadIdx.x & 31;
    int beg = g_offs[gw];
    int n = g_cnt[gw];
    float ax = 0.f, ay = 0.f;
    int j = 0;
    for (; j + 3 < n; j += 4) {
        int t0 = __ldg(&g_csr[beg + j + 0]);
        int t1 = __ldg(&g_csr[beg + j + 1]);
        int t2 = __ldg(&g_csr[beg + j + 2]);
        int t3 = __ldg(&g_csr[beg + j + 3]);
        float2 v0 = __half22float2(*(const __half2*)&g_h_task[t0 * 64 + lane * 2]);
        float2 v1 = __half22float2(*(const __half2*)&g_h_task[t1 * 64 + lane * 2]);
        float2 v2 = __half22float2(*(const __half2*)&g_h_task[t2 * 64 + lane * 2]);
        float2 v3 = __half22float2(*(const __half2*)&g_h_task[t3 * 64 + lane * 2]);
        ax += (v0.x + v1.x) + (v2.x + v3.x);
        ay += (v0.y + v1.y) + (v2.y + v3.y);
    }
    for (; j < n; j++) {
        int t = __ldg(&g_csr[beg + j]);
        float2 v = __half22float2(*(const __half2*)&g_h_task[t * 64 + lane * 2]);
        ax += v.x;
        ay += v.y;
    }
    float inv = (n > 0) ? 1.0f / (float)n : 0.f;
    float2 o;
    o.x = ax * inv;
    o.y = ay * inv;
    *(float2*)&out[(size_t)gw * 64 + lane * 2] = o;
}

// ---------------- launch ----------------
extern "C" void kernel_launch(void* const* d_in, const int* in_sizes, int n_in,
                              void* d_out, int out_size) {
    const float* feat_ret  = (const float*)d_in[0];
    const float* feat_dram = (const float*)d_in[1];
    const float* feat_link = (const float*)d_in[2];
    const float* W_ret   = (const float*)d_in[3];
    const float* b_ret   = (const float*)d_in[4];
    const float* W_dram  = (const float*)d_in[5];
    const float* b_dram  = (const float*)d_in[6];
    const float* W_link  = (const float*)d_in[7];
    const float* b_link  = (const float*)d_in[8];
    const float* W_task  = (const float*)d_in[9];
    const float* b_task  = (const float*)d_in[10];
    const int* task_ret  = (const int*)d_in[11];
    const int* mod_ret   = (const int*)d_in[12];
    const int* task_dram = (const int*)d_in[13];
    const int* mod_dram  = (const int*)d_in[14];
    const int* task_link = (const int*)d_in[15];
    const int* mod_link  = (const int*)d_in[16];
    float* out = (float*)d_out;

    const int TPB = 256;
    const int smem_task = 64 * 192 * 4 + 64 * 97 * 8 + 192 * 8 + 192 * 4 + 192 * 4;
    cudaFuncSetAttribute(k_task, cudaFuncAttributeMaxDynamicSharedMemorySize, smem_task);

    k_init<<<(N_LINKN + TPB - 1) / TPB, TPB>>>();

    // segment sums + g_mm init in tail range
    k_sum<<<(NE_ALL + 3 * N_TASK + TPB - 1) / TPB, TPB>>>(feat_link, mod_link,
                                                          feat_ret,  mod_ret,
                                                          feat_dram, mod_dram);

    // scan (98 blocks) fused with ret/dram minmax
    k_fuse<<<SCAN_NBLK + (E_RET + E_DRAM + TPB - 1) / TPB, TPB>>>(mod_ret,  task_ret,
                                                                  mod_dram, task_dram);

    k_mm_link<<<(E_LINK + TPB - 1) / TPB, TPB>>>(mod_link, task_link);

    k_task<<<(N_TASK + 63) / 64, TPB, smem_task>>>(W_ret, b_ret, W_dram, b_dram,
                                                   W_link, b_link, W_task, b_task);

    k_linkmean<<<(N_LINKN * 32 + TPB - 1) / TPB, TPB>>>(out);
}

// round 10
// speedup vs baseline: 1.0812x; 1.0812x over previous
#include <cuda_runtime.h>
#include <cuda_fp16.h>

#define N_TASK 50000
#define N_RET  20000
#define N_DRAM 5000
#define N_LINKN 100000
#define E_RET  1000000
#define E_DRAM 250000
#define E_LINK 2000000
#define HD 64
#define SCAN_NBLK 98   /* ceil(100000/1024) */

// ---------------- device scratch ----------------
__device__ float    g_s_ret[N_RET];
__device__ float    g_s_dram[N_DRAM];
__device__ float2   g_sc_link[N_LINKN];   // (sum, count) -> after scan: (sum, offs-bits)
__device__ uint2    g_mm[3 * N_TASK];     // (max_enc, min_enc) per (etype, task)
__device__ __half   g_h_task[N_TASK * HD];
__device__ int      g_cnt[N_LINKN];
__device__ int      g_offs[N_LINKN];
__device__ int      g_rank[E_LINK];       // edge's rank within its module
__device__ int      g_csr[E_LINK];
__device__ int      g_part[128];
__device__ int      g_done;

// order-preserving float<->uint encoding (all real floats encode > 0)
__device__ __forceinline__ unsigned encf(float f) {
    unsigned u = __float_as_uint(f);
    return (u & 0x80000000u) ? ~u : (u | 0x80000000u);
}
__device__ __forceinline__ float decf(unsigned u) {
    return __uint_as_float((u & 0x80000000u) ? (u & 0x7FFFFFFFu) : ~u);
}

__device__ __forceinline__ float tanh_fast(float x) {
    float y;
    asm("tanh.approx.f32 %0, %1;" : "=f"(y) : "f"(x));
    return y;
}

// ---------------- init ----------------
__global__ void k_init() {
    int i = blockIdx.x * blockDim.x + threadIdx.x;
    if (i == 0) g_done = 0;
    if (i < N_RET)  g_s_ret[i]  = 0.f;
    if (i < N_DRAM) g_s_dram[i] = 0.f;
    if (i < N_LINKN) g_sc_link[i] = make_float2(0.f, 0.f);
    if (i < N_TASK) {
#pragma unroll
        for (int et = 0; et < 3; et++)
            g_mm[et * N_TASK + i] = make_uint2(0u, 0xFFFFFFFFu);
    }
}

// ---------------- fused segment sums: 1 edge / thread ----------------
__global__ void k_sum(const float* __restrict__ fl, const int* __restrict__ ml,
                      const float* __restrict__ fr, const int* __restrict__ mr,
                      const float* __restrict__ fd, const int* __restrict__ md) {
    int i = blockIdx.x * blockDim.x + threadIdx.x;
    if (i < E_LINK) {
        int m = __ldg(&ml[i]);
        float2 old = atomicAdd(&g_sc_link[m], make_float2(__ldg(&fl[i]), 1.0f));
        g_rank[i] = (int)old.y;           // this edge's rank within module m
    } else if (i < E_LINK + E_RET) {
        int j = i - E_LINK;
        atomicAdd(&g_s_ret[__ldg(&mr[j])], __ldg(&fr[j]));
    } else if (i < E_LINK + E_RET + E_DRAM) {
        int j = i - E_LINK - E_RET;
        atomicAdd(&g_s_dram[__ldg(&md[j])], __ldg(&fd[j]));
    }
}

// ---------------- single-kernel scan: publish partial, spin-join, resume ---
// grid = 98 blocks < 148 SMs -> all co-resident in wave 1 -> spin is safe.
__global__ void k_scan() {
    __shared__ int sh[256];
    int b = blockIdx.x, tid = threadIdx.x;
    int i = b * 1024 + tid * 4;

    int c0 = 0, c1 = 0, c2 = 0, c3 = 0, s = 0;
    if (i < N_LINKN) {
        float4 a = *(const float4*)&g_sc_link[i];
        float4 d = *(const float4*)&g_sc_link[i + 2];
        c0 = (int)a.y; c1 = (int)a.w; c2 = (int)d.y; c3 = (int)d.w;
        s = c0 + c1 + c2 + c3;
    }

    sh[tid] = s;
    __syncthreads();
    for (int off = 1; off < 256; off <<= 1) {
        int u = (tid >= off) ? sh[tid - off] : 0;
        __syncthreads();
        sh[tid] += u;
        __syncthreads();
    }
    int incl = sh[tid];
    int blk_total = sh[255];

    if (tid == 0) {
        g_part[b] = blk_total;
        __threadfence();
        atomicAdd(&g_done, 1);
        while (*(volatile int*)&g_done < SCAN_NBLK) { }
    }
    __syncthreads();

    sh[tid] = (tid < b) ? ((volatile int*)g_part)[tid] : 0;
    __syncthreads();
    for (int off = 128; off > 0; off >>= 1) {
        if (tid < off) sh[tid] += sh[tid + off];
        __syncthreads();
    }
    int base = sh[0];

    int run = base + incl - s;
    if (i < N_LINKN) {
        int4 o;
        o.x = run;
        o.y = run + c0;
        o.z = o.y + c1;
        o.w = o.z + c2;
        *(int4*)&g_offs[i] = o;
        *(int4*)&g_cnt[i]  = make_int4(c0, c1, c2, c3);
        int2* scl = (int2*)g_sc_link;
        scl[i + 0].y = o.x;
        scl[i + 1].y = o.y;
        scl[i + 2].y = o.z;
        scl[i + 3].y = o.w;
    }
}

// ---------------- fused per-task min/max (link branch also scatters CSR) --
__global__ void k_mm(const int* __restrict__ ml, const int* __restrict__ tl,
                     const int* __restrict__ mr, const int* __restrict__ tr,
                     const int* __restrict__ md, const int* __restrict__ td) {
    int i = blockIdx.x * blockDim.x + threadIdx.x;
    if (i < E_LINK) {
        int m = __ldg(&ml[i]);
        int t = __ldg(&tl[i]);
        float2 sc = *(const float2*)&g_sc_link[m];   // one 8B scattered load
        unsigned k = encf(sc.x);
        atomicMax(&g_mm[2 * N_TASK + t].x, k);
        atomicMin(&g_mm[2 * N_TASK + t].y, k);
        int p = __float_as_int(sc.y) + __ldg(&g_rank[i]);
        g_csr[p] = t;
    } else if (i < E_LINK + E_RET) {
        int j = i - E_LINK;
        unsigned k = encf(g_s_ret[__ldg(&mr[j])]);
        int t = __ldg(&tr[j]);
        atomicMax(&g_mm[0 * N_TASK + t].x, k);
        atomicMin(&g_mm[0 * N_TASK + t].y, k);
    } else if (i < E_LINK + E_RET + E_DRAM) {
        int j = i - E_LINK - E_RET;
        unsigned k = encf(g_s_dram[__ldg(&md[j])]);
        int t = __ldg(&td[j]);
        atomicMax(&g_mm[1 * N_TASK + t].x, k);
        atomicMin(&g_mm[1 * N_TASK + t].y, k);
    }
}

// ---------------- task update: tanh(v @ Wtask^T + b), f32x2 FFMA ----------
// Thread (lane tx, warp ty): columns h = tx and tx+32, tasks t0 = ty*8.
// Halves v-side LDS.128 broadcast traffic vs 1-col x 16-task layout.
__global__ void k_task(const float* __restrict__ Wret,  const float* __restrict__ bret,
                       const float* __restrict__ Wdram, const float* __restrict__ bdram,
                       const float* __restrict__ Wlink, const float* __restrict__ blink,
                       const float* __restrict__ Wtask, const float* __restrict__ btask) {
    extern __shared__ float sh[];
    float*  sV  = sh;                                   // 12288 floats
    float2* sW2 = (float2*)(sh + 64 * 192);             // 64*97 float2
    uint2*  sMM = (uint2*)(sh + 64 * 192 + 64 * 97 * 2);// 192 uint2
    float*  sWe = (float*)(sMM + 192);                  // 192 floats
    float*  sBe = sWe + 192;                            // 192 floats

    int tb = blockIdx.x * 64;
    int tid = threadIdx.x;

    if (tid < 192) {
        int et = tid >> 6, hh = tid & 63;
        const float* We = (et == 0) ? Wret : (et == 1) ? Wdram : Wlink;
        const float* be = (et == 0) ? bret : (et == 1) ? bdram : blink;
        sWe[tid] = We[hh];
        sBe[tid] = be[hh];
    }
    for (int idx = tid; idx < 64 * 3; idx += 256) {
        int tl = idx / 3, et = idx - tl * 3;
        int t = tb + tl;
        sMM[tl * 3 + et] = (t < N_TASK) ? g_mm[et * N_TASK + t]
                                        : make_uint2(0u, 0xFFFFFFFFu);
    }
    for (int idx = tid; idx < 64 * 96; idx += 256) {
        int h = idx / 96, kp = idx - h * 96;
        sW2[h * 97 + kp] = *(const float2*)&Wtask[h * 192 + 2 * kp];
    }
    __syncthreads();

    for (int idx = tid; idx < 64 * 192; idx += 256) {
        int tl = idx / 192, k = idx - tl * 192;
        int et = k >> 6, h = k & 63;
        float v = 0.f;
        uint2 mm = sMM[tl * 3 + et];
        if (mm.x != 0u) {
            float w = sWe[et * 64 + h];
            float sv = (w >= 0.f) ? decf(mm.x) : decf(mm.y);
            v = tanh_fast(fmaf(w, sv, sBe[et * 64 + h]));
        }
        sV[idx] = v;
    }
    __syncthreads();

    int tx = tid & 31, ty = tid >> 5;
    int t0 = ty * 8;                     // 8 tasks per thread
    // two h columns per thread: tx and tx+32

    unsigned long long acc0[8], acc1[8];
#pragma unroll
    for (int i = 0; i < 8; i++) { acc0[i] = 0ull; acc1[i] = 0ull; }

    const float2* w0row = sW2 + tx * 97;
    const float2* w1row = sW2 + (tx + 32) * 97;
    const float*  vb    = sV + t0 * 192;

#pragma unroll 4
    for (int kp = 0; kp < 96; kp += 2) {
        unsigned long long wa0 = *(const unsigned long long*)&w0row[kp];
        unsigned long long wa1 = *(const unsigned long long*)&w0row[kp + 1];
        unsigned long long wb0 = *(const unsigned long long*)&w1row[kp];
        unsigned long long wb1 = *(const unsigned long long*)&w1row[kp + 1];
#pragma unroll
        for (int i = 0; i < 8; i++) {
            ulonglong2 v = *(const ulonglong2*)(vb + i * 192 + 2 * kp);
            asm("fma.rn.f32x2 %0, %1, %2, %0;" : "+l"(acc0[i]) : "l"(v.x), "l"(wa0));
            asm("fma.rn.f32x2 %0, %1, %2, %0;" : "+l"(acc0[i]) : "l"(v.y), "l"(wa1));
            asm("fma.rn.f32x2 %0, %1, %2, %0;" : "+l"(acc1[i]) : "l"(v.x), "l"(wb0));
            asm("fma.rn.f32x2 %0, %1, %2, %0;" : "+l"(acc1[i]) : "l"(v.y), "l"(wb1));
        }
    }

    float bh0 = btask[tx], bh1 = btask[tx + 32];
#pragma unroll
    for (int i = 0; i < 8; i++) {
        int t = tb + t0 + i;
        if (t < N_TASK) {
            float lo, hi;
            asm("mov.b64 {%0, %1}, %2;" : "=f"(lo), "=f"(hi) : "l"(acc0[i]));
            g_h_task[t * 64 + tx] = __float2half(tanh_fast(lo + hi + bh0));
            asm("mov.b64 {%0, %1}, %2;" : "=f"(lo), "=f"(hi) : "l"(acc1[i]));
            g_h_task[t * 64 + tx + 32] = __float2half(tanh_fast(lo + hi + bh1));
        }
    }
}

// ---------------- link mean: warp per link node, CSR gather (fp16 h) ------
__global__ void k_linkmean(float* __restrict__ out) {
    int gw = (blockIdx.x * blockDim.x + threadIdx.x) >> 5;
    if (gw >= N_LINKN) return;
    int lane = threadIdx.x & 31;
    int beg = g_offs[gw];
    int n = g_cnt[gw];
    float ax = 0.f, ay = 0.f;
    int j = 0;
    for (; j + 3 < n; j += 4) {
        int t0 = __ldg(&g_csr[beg + j + 0]);
        int t1 = __ldg(&g_csr[beg + j + 1]);
        int t2 = __ldg(&g_csr[beg + j + 2]);
        int t3 = __ldg(&g_csr[beg + j + 3]);
        float2 v0 = __half22float2(*(const __half2*)&g_h_task[t0 * 64 + lane * 2]);
        float2 v1 = __half22float2(*(const __half2*)&g_h_task[t1 * 64 + lane * 2]);
        float2 v2 = __half22float2(*(const __half2*)&g_h_task[t2 * 64 + lane * 2]);
        float2 v3 = __half22float2(*(const __half2*)&g_h_task[t3 * 64 + lane * 2]);
        ax += (v0.x + v1.x) + (v2.x + v3.x);
        ay += (v0.y + v1.y) + (v2.y + v3.y);
    }
    for (; j < n; j++) {
        int t = __ldg(&g_csr[beg + j]);
        float2 v = __half22float2(*(const __half2*)&g_h_task[t * 64 + lane * 2]);
        ax += v.x;
        ay += v.y;
    }
    float inv = (n > 0) ? 1.0f / (float)n : 0.f;
    float2 o;
    o.x = ax * inv;
    o.y = ay * inv;
    *(float2*)&out[(size_t)gw * 64 + lane * 2] = o;
}

// ---------------- launch ----------------
extern "C" void kernel_launch(void* const* d_in, const int* in_sizes, int n_in,
                              void* d_out, int out_size) {
    const float* feat_ret  = (const float*)d_in[0];
    const float* feat_dram = (const float*)d_in[1];
    const float* feat_link = (const float*)d_in[2];
    const float* W_ret   = (const float*)d_in[3];
    const float* b_ret   = (const float*)d_in[4];
    const float* W_dram  = (const float*)d_in[5];
    const float* b_dram  = (const float*)d_in[6];
    const float* W_link  = (const float*)d_in[7];
    const float* b_link  = (const float*)d_in[8];
    const float* W_task  = (const float*)d_in[9];
    const float* b_task  = (const float*)d_in[10];
    const int* task_ret  = (const int*)d_in[11];
    const int* mod_ret   = (const int*)d_in[12];
    const int* task_dram = (const int*)d_in[13];
    const int* mod_dram  = (const int*)d_in[14];
    const int* task_link = (const int*)d_in[15];
    const int* mod_link  = (const int*)d_in[16];
    float* out = (float*)d_out;

    const int TPB = 256;
    const int NE = E_LINK + E_RET + E_DRAM;  // 3,250,000
    const int smem_task = 64 * 192 * 4 + 64 * 97 * 8 + 192 * 8 + 192 * 4 + 192 * 4;
    cudaFuncSetAttribute(k_task, cudaFuncAttributeMaxDynamicSharedMemorySize, smem_task);

    k_init<<<(N_LINKN + TPB - 1) / TPB, TPB>>>();

    k_sum<<<(NE + TPB - 1) / TPB, TPB>>>(feat_link, mod_link,
                                         feat_ret,  mod_ret,
                                         feat_dram, mod_dram);

    k_scan<<<SCAN_NBLK, 256>>>();

    k_mm<<<(NE + TPB - 1) / TPB, TPB>>>(mod_link, task_link,
                                        mod_ret,  task_ret,
                                        mod_dram, task_dram);

    k_task<<<(N_TASK + 63) / 64, TPB, smem_task>>>(W_ret, b_ret, W_dram, b_dram,
                                                   W_link, b_link, W_task, b_task);

    k_linkmean<<<(N_LINKN * 32 + TPB - 1) / TPB, TPB>>>(out);
}